// round 1
// baseline (speedup 1.0000x reference)
#include <cuda_runtime.h>
#include <math.h>

// Problem constants
#define B_  16
#define N_  1024
#define P_  8
#define H_  300

// Scratch (device globals — no allocation allowed)
__device__ float g_W2[B_ * P_ * H_ * H_];        // 46 MB: instr*sim folded weights
__device__ float g_Y[(size_t)B_ * P_ * N_ * H_]; // 157 MB: scaled = A @ W2
__device__ float g_logits[B_ * N_];

// ---------------------------------------------------------------------------
// f32x2 helpers (Blackwell packed-pair FMA: 2x fp32 throughput vs FFMA-3reg)
// ---------------------------------------------------------------------------
__device__ __forceinline__ unsigned long long fma2(unsigned long long a,
                                                   unsigned long long b,
                                                   unsigned long long c) {
    unsigned long long d;
    asm("fma.rn.f32x2 %0, %1, %2, %3;" : "=l"(d) : "l"(a), "l"(b), "l"(c));
    return d;
}
__device__ __forceinline__ unsigned long long pack2(float x) {
    unsigned long long d;
    asm("mov.b64 %0, {%1, %1};" : "=l"(d) : "f"(x));
    return d;
}
__device__ __forceinline__ float lo2(unsigned long long v) {
    return __uint_as_float((unsigned)(v & 0xffffffffull));
}
__device__ __forceinline__ float hi2(unsigned long long v) {
    return __uint_as_float((unsigned)(v >> 32));
}

__device__ __forceinline__ float warp_sum(float v) {
#pragma unroll
    for (int o = 16; o; o >>= 1) v += __shfl_xor_sync(0xffffffffu, v, o);
    return v;
}
__device__ __forceinline__ float warp_max(float v) {
#pragma unroll
    for (int o = 16; o; o >>= 1) v = fmaxf(v, __shfl_xor_sync(0xffffffffu, v, o));
    return v;
}

// ---------------------------------------------------------------------------
// K1: W2[b,p,h,k] = instruction[b,h] * sim[b,p] * W[p,h,k]
// One float4 per thread. total = B*P*H*(H/4) = 2,880,000 float4s
// ---------------------------------------------------------------------------
__global__ void prep_w2_kernel(const float* __restrict__ instr,
                               const float* __restrict__ sim,
                               const float* __restrict__ W) {
    int idx = blockIdx.x * blockDim.x + threadIdx.x;
    const int total = B_ * P_ * H_ * (H_ / 4);
    if (idx >= total) return;
    int c4  = idx % (H_ / 4);          // float4 index along k
    int row = idx / (H_ / 4);          // b*P*H + p*H + h
    int h   = row % H_;
    int bp  = row / H_;
    int p   = bp % P_;
    int b   = bp / P_;
    float s = instr[b * H_ + h] * sim[b * P_ + p];
    float4 w = *(const float4*)(W + (size_t)(p * H_ + h) * H_ + 4 * c4);
    w.x *= s; w.y *= s; w.z *= s; w.w *= s;
    *(float4*)(g_W2 + (size_t)4 * idx) = w;
}

// ---------------------------------------------------------------------------
// K2: batched SGEMM.  For each bp in [0,128):
//   Y[bp][n][k] = sum_h A[n][h] * W2[bp][h][k],  M=1024, N=300, K=300
//   A[n][h] = node_attr + b*N*P*H + p*H + n*(P*H) + h
// Block tile 128(M) x 64(Nc), Ktile 16. 256 threads, thread tile 8x4 as
// 4 m-pairs x 4 cols in f32x2 registers.
// ---------------------------------------------------------------------------
#define MT 128
#define NT 64
#define KT 16

__global__ __launch_bounds__(256)
void gemm_kernel(const float* __restrict__ node_attr) {
    const int bp = blockIdx.z;            // 0..127
    const int b  = bp >> 3;
    const int p  = bp & 7;
    const float* Abase = node_attr + (size_t)b * N_ * P_ * H_ + (size_t)p * H_;
    const float* Bbase = g_W2 + (size_t)bp * H_ * H_;
    float*       Cbase = g_Y  + (size_t)bp * N_ * H_;

    const int m0 = blockIdx.y * MT;
    const int n0 = blockIdx.x * NT;

    __shared__ float As[KT][MT];   // k-major for column access
    __shared__ float Bs[KT][NT];

    const int t  = threadIdx.x;
    const int tn = t & 15;    // owns cols n0 + 4*tn .. +3
    const int tm = t >> 4;    // owns rows m0 + 8*tm .. +7

    unsigned long long c[4][4];
#pragma unroll
    for (int i = 0; i < 4; i++)
#pragma unroll
        for (int j = 0; j < 4; j++) c[i][j] = 0ull;

    for (int kt = 0; kt < H_; kt += KT) {
        // ---- load A tile: 128 rows x 16 h, 512 float4s, coalesced ----
#pragma unroll
        for (int i = 0; i < 2; i++) {
            int u   = i * 256 + t;
            int row = u >> 2;
            int h4  = (u & 3) * 4;
            int h   = kt + h4;
            float4 v = make_float4(0.f, 0.f, 0.f, 0.f);
            if (h < H_)
                v = *(const float4*)(Abase + (size_t)(m0 + row) * (P_ * H_) + h);
            As[h4 + 0][row] = v.x;
            As[h4 + 1][row] = v.y;
            As[h4 + 2][row] = v.z;
            As[h4 + 3][row] = v.w;
        }
        // ---- load B tile: 16 h x 64 cols, 256 float4s ----
        {
            int k   = t >> 4;
            int c4  = (t & 15) * 4;
            int h   = kt + k;
            int col = n0 + c4;
            float4 v = make_float4(0.f, 0.f, 0.f, 0.f);
            if (h < H_ && col < H_)
                v = *(const float4*)(Bbase + (size_t)h * H_ + col);
            *(float4*)&Bs[k][c4] = v;
        }
        __syncthreads();

#pragma unroll
        for (int k = 0; k < KT; k++) {
            unsigned long long a0 = *(const unsigned long long*)&As[k][8 * tm + 0];
            unsigned long long a1 = *(const unsigned long long*)&As[k][8 * tm + 2];
            unsigned long long a2 = *(const unsigned long long*)&As[k][8 * tm + 4];
            unsigned long long a3 = *(const unsigned long long*)&As[k][8 * tm + 6];
            float4 bv = *(const float4*)&Bs[k][4 * tn];
            unsigned long long b0 = pack2(bv.x);
            unsigned long long b1 = pack2(bv.y);
            unsigned long long b2 = pack2(bv.z);
            unsigned long long b3 = pack2(bv.w);
            c[0][0] = fma2(a0, b0, c[0][0]); c[0][1] = fma2(a0, b1, c[0][1]);
            c[0][2] = fma2(a0, b2, c[0][2]); c[0][3] = fma2(a0, b3, c[0][3]);
            c[1][0] = fma2(a1, b0, c[1][0]); c[1][1] = fma2(a1, b1, c[1][1]);
            c[1][2] = fma2(a1, b2, c[1][2]); c[1][3] = fma2(a1, b3, c[1][3]);
            c[2][0] = fma2(a2, b0, c[2][0]); c[2][1] = fma2(a2, b1, c[2][1]);
            c[2][2] = fma2(a2, b2, c[2][2]); c[2][3] = fma2(a2, b3, c[2][3]);
            c[3][0] = fma2(a3, b0, c[3][0]); c[3][1] = fma2(a3, b1, c[3][1]);
            c[3][2] = fma2(a3, b2, c[3][2]); c[3][3] = fma2(a3, b3, c[3][3]);
        }
        __syncthreads();
    }

    // ---- store ----
    const int col = n0 + 4 * tn;
    if (col < H_) {
#pragma unroll
        for (int i = 0; i < 4; i++) {
            size_t r = (size_t)(m0 + 8 * tm + 2 * i);
            float4 lo4 = make_float4(lo2(c[i][0]), lo2(c[i][1]), lo2(c[i][2]), lo2(c[i][3]));
            float4 hi4 = make_float4(hi2(c[i][0]), hi2(c[i][1]), hi2(c[i][2]), hi2(c[i][3]));
            *(float4*)(Cbase + r * H_ + col)       = lo4;
            *(float4*)(Cbase + (r + 1) * H_ + col) = hi4;
        }
    }
}

// ---------------------------------------------------------------------------
// K3: per-(b,n) epilogue: reduce over P, normalize, elu, dot with wss, + mask
// One block (256 thr) per (b,n) row.
// ---------------------------------------------------------------------------
__global__ __launch_bounds__(256)
void epilogue_kernel(const float* __restrict__ wss,
                     const float* __restrict__ mask) {
    const int bn = blockIdx.x;       // b*N + n
    const int b  = bn >> 10;
    const int n  = bn & 1023;
    const float* base = g_Y + (size_t)b * P_ * N_ * H_ + (size_t)n * H_;

    float acc = 0.f;
    for (int k = threadIdx.x; k < H_; k += blockDim.x) {
        float s = 0.f, q = 0.f;
#pragma unroll
        for (int p = 0; p < P_; p++) {
            float v = base[(size_t)p * (N_ * H_) + k];
            s += v;
            q = fmaf(v, v, q);
        }
        float nrm = fmaxf(sqrtf(q), 1e-12f);
        float sc  = s / nrm;
        float e   = sc > 0.f ? sc : expm1f(sc);
        acc += e * wss[k];
    }
    acc = warp_sum(acc);
    __shared__ float ws[8];
    int lane = threadIdx.x & 31, wid = threadIdx.x >> 5;
    if (lane == 0) ws[wid] = acc;
    __syncthreads();
    if (threadIdx.x == 0) {
        float s = 0.f;
#pragma unroll
        for (int i = 0; i < 8; i++) s += ws[i];
        g_logits[bn] = s + mask[bn];
    }
}

// ---------------------------------------------------------------------------
// K4: softmax over N per batch. 16 blocks x 1024 threads.
// ---------------------------------------------------------------------------
__global__ __launch_bounds__(1024)
void softmax_kernel(float* __restrict__ out) {
    const int b = blockIdx.x, t = threadIdx.x;
    const float v = g_logits[b * N_ + t];
    __shared__ float red[32];
    const int lane = t & 31, wid = t >> 5;

    // max over 1024
    float m = warp_max(v);
    if (lane == 0) red[wid] = m;
    __syncthreads();
    if (wid == 0) {
        float x = red[lane];
        x = warp_max(x);
        red[lane] = x;
    }
    __syncthreads();
    m = red[0];
    __syncthreads();

    float e = expf(v - m);
    float s = warp_sum(e);
    if (lane == 0) red[wid] = s;
    __syncthreads();
    if (wid == 0) {
        float x = red[lane];
        x = warp_sum(x);
        red[lane] = x;
    }
    __syncthreads();
    s = red[0];

    out[b * N_ + t] = e / s;
}

// ---------------------------------------------------------------------------
// launch
// inputs: 0 node_attr (B,N,P,H) | 1 edge_attr | 2 instruction (B,H)
//         3 distribution | 4 node_prop_similarities (B,P) | 5 node_mask (B,N)
//         6 weight_node_properties (P,H,H) | 7 weight_state_score (H) | 8 ins_id
// ---------------------------------------------------------------------------
extern "C" void kernel_launch(void* const* d_in, const int* in_sizes, int n_in,
                              void* d_out, int out_size) {
    const float* node_attr = (const float*)d_in[0];
    const float* instr     = (const float*)d_in[2];
    const float* sim       = (const float*)d_in[4];
    const float* mask      = (const float*)d_in[5];
    const float* W         = (const float*)d_in[6];
    const float* wss       = (const float*)d_in[7];
    float* out = (float*)d_out;

    // K1: fold instruction & similarity into weights
    const int total1 = B_ * P_ * H_ * (H_ / 4);
    prep_w2_kernel<<<(total1 + 255) / 256, 256>>>(instr, sim, W);

    // K2: batched SGEMM
    dim3 g2((H_ + NT - 1) / NT, N_ / MT, B_ * P_);   // (5, 8, 128)
    gemm_kernel<<<g2, 256>>>(node_attr);

    // K3: epilogue -> logits
    epilogue_kernel<<<B_ * N_, 256>>>(wss, mask);

    // K4: softmax -> out
    softmax_kernel<<<B_, 1024>>>(out);
}